// round 16
// baseline (speedup 1.0000x reference)
#include <cuda_runtime.h>
#include <cuda_fp16.h>
#include <mma.h>
#include <cstdint>
#include <cstddef>

#define NMAX 100000
#define EMAX 600000
#define NG   256
#define DH   128
#define H4   512
#define BN_EPS 1e-5f
#define GN_EPS 1e-5f

using namespace nvcuda;

// ---------------- static device scratch ----------------
static __device__ __half g_Ah[(size_t)NMAX * DH];
static __device__ __half g_Al[(size_t)NMAX * DH];
static __device__ float g_z1[(size_t)NMAX * H4];
static __device__ float g_z2[(size_t)NMAX * DH];
static __device__ float g_h [(size_t)NMAX * DH];
static __device__ __half g_W1h[4 * H4 * DH];
static __device__ __half g_W2h[4 * DH * H4];
static __device__ __half g_W2l[4 * DH * H4];
static __device__ int   g_rowptr[NMAX + 1];
static __device__ int   g_cursor[NMAX];
static __device__ int   g_colidx[EMAX];
static __device__ int   g_bsum[128];
static __device__ int   g_boff[128];
static __device__ int   g_gstart[NG + 1];
static __device__ float g_invcnt[NG];
static __device__ float g_bnstat[2 * H4];
static __device__ float g_gsum[NG * DH];
static __device__ float g_gsq[NG * DH];
static __device__ int   g_i64;

// ---------------- helpers ----------------
__device__ __forceinline__ float selu_f(float x) {
    const float lam = 1.0507009873554805f;
    const float la  = 1.7580993408473766f;
    return x > 0.f ? lam * x : la * (__expf(x) - 1.f);
}
__device__ __forceinline__ int readIdx(const void* p, long long i) {
    return g_i64 ? (int)((const long long*)p)[i] : ((const int*)p)[i];
}
__device__ __forceinline__ void split2h(float a, float b, uint32_t& hi, uint32_t& lo) {
    __half2 H = __floats2half2_rn(a, b);
    float2 F = __half22float2(H);
    __half2 L = __floats2half2_rn(a - F.x, b - F.y);
    hi = *(uint32_t*)&H;
    lo = *(uint32_t*)&L;
}
__device__ __forceinline__ void cpa16(uint32_t dst, const void* src, int srcsz) {
    asm volatile("cp.async.cg.shared.global [%0], [%1], 16, %2;"
                 :: "r"(dst), "l"(src), "r"(srcsz));
}
#define CPA_COMMIT() asm volatile("cp.async.commit_group;" ::: "memory")
#define CPA_WAIT0()  asm volatile("cp.async.wait_group 0;" ::: "memory")
#define CPA_WAIT1()  asm volatile("cp.async.wait_group 1;" ::: "memory")

// GEMM1: K=64 chunk tiles, 128 rows x 64 fp16, row stride 72 elems (144B)
#define LDA64 72
#define ROW64 144
#define T64   18432
#define SET64 (3 * T64)                 // {Ah, Al, Bh} = 55296
#define SMEM_G1 (2 * SET64)             // 110592 -> 2 CTAs/SM

// GEMM2: K=32 chunk tiles, 128 rows x 32 fp16, row stride 40 elems (80B)
#define LDA2 40
#define ROWB 80
#define T32  10240
#define SET_G2 (4 * T32)                // {Ah, Al, Bh, Bl} = 40960
#define G2_STG  (2 * SET_G2)            // 81920
#define SMEM_G2 (G2_STG + 128 * 144)    // 100352
#define LDC 132

// ---------------- GEMM1 MMA: one 128x128x64 chunk, 2-term, warp tile 32x64 ------
__device__ __forceinline__ void mma_chunk64(
    const char* bc, int m0, int n0,
    wmma::fragment<wmma::accumulator, 16, 16, 16, float> acc[2][4]) {
    const __half* Ah = (const __half*)bc;
    const __half* Al = (const __half*)(bc + T64);
    const __half* Bh = (const __half*)(bc + 2 * T64);
#pragma unroll
    for (int ks = 0; ks < 4; ks++) {
        wmma::fragment<wmma::matrix_a, 16, 16, 16, __half, wmma::row_major> ah[2], al[2];
#pragma unroll
        for (int mi = 0; mi < 2; mi++) {
            wmma::load_matrix_sync(ah[mi], Ah + (m0 + 16 * mi) * LDA64 + ks * 16, LDA64);
            wmma::load_matrix_sync(al[mi], Al + (m0 + 16 * mi) * LDA64 + ks * 16, LDA64);
        }
#pragma unroll
        for (int ni = 0; ni < 4; ni++) {
            wmma::fragment<wmma::matrix_b, 16, 16, 16, __half, wmma::col_major> bh;
            wmma::load_matrix_sync(bh, Bh + (n0 + 16 * ni) * LDA64 + ks * 16, LDA64);
#pragma unroll
            for (int mi = 0; mi < 2; mi++) {
                wmma::mma_sync(acc[mi][ni], ah[mi], bh, acc[mi][ni]);
                wmma::mma_sync(acc[mi][ni], al[mi], bh, acc[mi][ni]);
            }
        }
    }
}

__device__ __forceinline__ void issueG1(const __half* __restrict__ Bh,
                                        int K, int rowBase, int M, int colBase,
                                        int kbase, uint32_t sb, int tid) {
#pragma unroll
    for (int i = 0; i < 12; i++) {      // 3 tiles x 128 rows x 8 k16
        int c = tid + i * 256;
        int tile = c >> 10, r = (c >> 3) & 127, k16 = c & 7;
        uint32_t dst = sb + tile * T64 + r * ROW64 + k16 * 16;
        const __half* src;
        int sz = 16;
        if (tile < 2) {
            int gr = rowBase + r;
            int cl = gr < M ? gr : (M - 1);
            sz = gr < M ? 16 : 0;
            src = (tile ? g_Al : g_Ah) + (size_t)cl * K + kbase + k16 * 8;
        } else {
            src = Bh + (size_t)(colBase + r) * K + kbase + k16 * 8;
        }
        cpa16(dst, src, sz);
    }
    CPA_COMMIT();
}

__global__ void __launch_bounds__(256, 2)
mgemm1(const __half* __restrict__ Bh, float* __restrict__ C, int M, int K, int Ncols) {
    extern __shared__ char sm[];
    uint32_t sb = (uint32_t)__cvta_generic_to_shared(sm);
    int tid = threadIdx.x;
    int w = tid >> 5;
    int m0 = (w >> 1) * 32, n0 = (w & 1) * 64;
    int rowBase = blockIdx.y * 128;
    int colBase = blockIdx.x * 128;

    wmma::fragment<wmma::accumulator, 16, 16, 16, float> acc[2][4];
#pragma unroll
    for (int mi = 0; mi < 2; mi++)
#pragma unroll
        for (int ni = 0; ni < 4; ni++) wmma::fill_fragment(acc[mi][ni], 0.f);

    // K=128 -> two K=64 chunks, both issued up front
    issueG1(Bh, K, rowBase, M, colBase, 0, sb, tid);
    issueG1(Bh, K, rowBase, M, colBase, 64, sb + SET64, tid);
    CPA_WAIT1();
    __syncthreads();
    mma_chunk64(sm, m0, n0, acc);
    CPA_WAIT0();
    __syncthreads();
    mma_chunk64(sm + SET64, m0, n0, acc);
    __syncthreads();

    // epilogue: stage in smem, write C, BN stats
    float* Csm = (float*)sm;
#pragma unroll
    for (int mi = 0; mi < 2; mi++)
#pragma unroll
        for (int ni = 0; ni < 4; ni++)
            wmma::store_matrix_sync(Csm + (m0 + 16 * mi) * LDC + n0 + 16 * ni,
                                    acc[mi][ni], LDC, wmma::mem_row_major);
    __syncthreads();
    {
        int row = tid >> 1;
        int cb = (tid & 1) * 64;
        int grow = rowBase + row;
        if (grow < M) {
            float* dst = C + (size_t)grow * Ncols + colBase + cb;
            const float* srcr = Csm + row * LDC + cb;
#pragma unroll
            for (int j = 0; j < 64; j += 4)
                *(float4*)(dst + j) = *(const float4*)(srcr + j);
        }
    }
    {
        int c = tid & 127;
        int r0 = (tid >> 7) * 64;
        float s = 0.f, q = 0.f;
#pragma unroll 4
        for (int r = r0; r < r0 + 64; r++) {
            float v = Csm[r * LDC + c];
            s += v; q += v * v;
        }
        atomicAdd(&g_bnstat[colBase + c], s);
        atomicAdd(&g_bnstat[H4 + colBase + c], q);
    }
}

// ---------------- GEMM2 (unchanged r15): 3-term, staged fp32 A ----------------
__device__ __forceinline__ void mma_chunk32g2(
    const char* bc, int m0, int n0,
    wmma::fragment<wmma::accumulator, 16, 16, 16, float> acc[2][4]) {
    const __half* Ah = (const __half*)bc;
    const __half* Al = (const __half*)(bc + T32);
    const __half* Bh = (const __half*)(bc + 2 * T32);
    const __half* Bl = (const __half*)(bc + 3 * T32);
#pragma unroll
    for (int ks = 0; ks < 2; ks++) {
        wmma::fragment<wmma::matrix_a, 16, 16, 16, __half, wmma::row_major> ah[2], al[2];
#pragma unroll
        for (int mi = 0; mi < 2; mi++) {
            wmma::load_matrix_sync(ah[mi], Ah + (m0 + 16 * mi) * LDA2 + ks * 16, LDA2);
            wmma::load_matrix_sync(al[mi], Al + (m0 + 16 * mi) * LDA2 + ks * 16, LDA2);
        }
#pragma unroll
        for (int ni = 0; ni < 4; ni++) {
            wmma::fragment<wmma::matrix_b, 16, 16, 16, __half, wmma::col_major> bh, bl;
            wmma::load_matrix_sync(bh, Bh + (n0 + 16 * ni) * LDA2 + ks * 16, LDA2);
            wmma::load_matrix_sync(bl, Bl + (n0 + 16 * ni) * LDA2 + ks * 16, LDA2);
#pragma unroll
            for (int mi = 0; mi < 2; mi++) {
                wmma::mma_sync(acc[mi][ni], ah[mi], bh, acc[mi][ni]);
                wmma::mma_sync(acc[mi][ni], al[mi], bh, acc[mi][ni]);
                wmma::mma_sync(acc[mi][ni], ah[mi], bl, acc[mi][ni]);
            }
        }
    }
}
__device__ __forceinline__ void issueA2(const float* __restrict__ A, int K,
                                        int rowBase, int M, int kbase,
                                        uint32_t sb, int tid) {
#pragma unroll
    for (int i = 0; i < 4; i++) {
        int c = tid + i * 256;
        int row = c >> 3, j = c & 7;
        int gr = rowBase + row;
        int cl = gr < M ? gr : (M - 1);
        int sz = gr < M ? 16 : 0;
        cpa16(sb + G2_STG + row * 144 + j * 16,
              A + (size_t)cl * K + kbase + j * 4, sz);
    }
}
__device__ __forceinline__ void issueB2(const __half* __restrict__ Bh,
                                        const __half* __restrict__ Bl,
                                        int K, int kbase, uint32_t sbset, int tid) {
#pragma unroll
    for (int i = 0; i < 4; i++) {
        int c = tid + i * 256;
        int half_ = c >> 9, r = (c >> 2) & 127, k16 = c & 3;
        const __half* src = (half_ ? Bl : Bh) + (size_t)r * K + kbase + k16 * 8;
        cpa16(sbset + (2 + half_) * T32 + r * ROWB + k16 * 16, src, 16);
    }
}
__device__ __forceinline__ void convertA(char* sm, char* dset, int kbase, int tid,
                                         const float* s_sc, const float* s_sh) {
    int kc = tid & 15;
    int rg = tid >> 4;
    float s0 = s_sc[kbase + 2 * kc],     b0 = s_sh[kbase + 2 * kc];
    float s1 = s_sc[kbase + 2 * kc + 1], b1 = s_sh[kbase + 2 * kc + 1];
    const char* stg = sm + G2_STG;
    char* tah = dset;
    char* tal = dset + T32;
#pragma unroll
    for (int rr = 0; rr < 8; rr++) {
        int row = rg * 8 + rr;
        float2 v = *(const float2*)(stg + row * 144 + kc * 8);
        float a = selu_f(fmaf(v.x, s0, b0));
        float b = selu_f(fmaf(v.y, s1, b1));
        uint32_t h, l;
        split2h(a, b, h, l);
        *(uint32_t*)(tah + row * ROWB + kc * 4) = h;
        *(uint32_t*)(tal + row * ROWB + kc * 4) = l;
    }
}

__global__ void __launch_bounds__(256, 2)
mgemm2(const float* __restrict__ A, const __half* __restrict__ Bh,
       const __half* __restrict__ Bl,
       float* __restrict__ C, int M, int K, int Ncols, const float* __restrict__ bias,
       const float* __restrict__ bn_g, const float* __restrict__ bn_b, float invN) {
    extern __shared__ char sm[];
    __shared__ float s_sc[H4], s_sh[H4];
    uint32_t sb = (uint32_t)__cvta_generic_to_shared(sm);
    int tid = threadIdx.x;
    int w = tid >> 5;
    int m0 = (w >> 1) * 32, n0 = (w & 1) * 64;
    int rowBase = blockIdx.y * 128;

    for (int i = tid; i < H4; i += 256) {
        float mu = g_bnstat[i] * invN;
        float var = fmaxf(g_bnstat[H4 + i] * invN - mu * mu, 0.f);
        float rstd = rsqrtf(var + BN_EPS);
        float sc = __ldg(&bn_g[i]) * rstd;
        s_sc[i] = sc;
        s_sh[i] = __ldg(&bn_b[i]) - mu * sc;
    }

    wmma::fragment<wmma::accumulator, 16, 16, 16, float> acc[2][4];
#pragma unroll
    for (int mi = 0; mi < 2; mi++)
#pragma unroll
        for (int ni = 0; ni < 4; ni++) wmma::fill_fragment(acc[mi][ni], 0.f);

    int nch = K >> 5;       // 16
    issueA2(A, K, rowBase, M, 0, sb, tid);
    issueB2(Bh, Bl, K, 0, sb, tid);
    CPA_COMMIT();
    CPA_WAIT0();
    __syncthreads();
    convertA(sm, sm, 0, tid, s_sc, s_sh);
    __syncthreads();

    for (int ch = 0; ch < nch; ch++) {
        if (ch + 1 < nch) {
            issueA2(A, K, rowBase, M, (ch + 1) * 32, sb, tid);
            issueB2(Bh, Bl, K, (ch + 1) * 32, sb + ((ch + 1) & 1) * SET_G2, tid);
            CPA_COMMIT();
        }
        mma_chunk32g2(sm + (ch & 1) * SET_G2, m0, n0, acc);
        if (ch + 1 < nch) {
            CPA_WAIT0();
            __syncthreads();
            convertA(sm, sm + ((ch + 1) & 1) * SET_G2, (ch + 1) * 32, tid, s_sc, s_sh);
        }
        __syncthreads();
    }

    float* Csm = (float*)sm;
#pragma unroll
    for (int mi = 0; mi < 2; mi++)
#pragma unroll
        for (int ni = 0; ni < 4; ni++)
            wmma::store_matrix_sync(Csm + (m0 + 16 * mi) * LDC + n0 + 16 * ni,
                                    acc[mi][ni], LDC, wmma::mem_row_major);
    __syncthreads();
    {
        int row = tid >> 1;
        int cb = (tid & 1) * 64;
        int grow = rowBase + row;
        if (grow < M) {
            float* dst = C + (size_t)grow * Ncols + cb;
            const float* srcr = Csm + row * LDC + cb;
#pragma unroll
            for (int j = 0; j < 64; j += 4) {
                float4 v = *(const float4*)(srcr + j);
                v.x += __ldg(&bias[cb + j + 0]);
                v.y += __ldg(&bias[cb + j + 1]);
                v.z += __ldg(&bias[cb + j + 2]);
                v.w += __ldg(&bias[cb + j + 3]);
                *(float4*)(dst + j) = v;
            }
        }
    }
}

// ---------------- setup kernels ----------------
__global__ void detect_zero_k(const void* ei, int n, float* out, int outn) {
    int i = blockIdx.x * blockDim.x + threadIdx.x;
    if (i < n) g_cursor[i] = 0;
    if (i < outn) out[i] = 0.f;
    if (i == 0) {
        const long long* p = (const long long*)ei;
        int ok = 1;
        for (int j = 0; j < 64; j++) {
            long long v = p[j];
            if (v < 0 || v >= (1LL << 31)) ok = 0;
        }
        g_i64 = ok;
    }
}
__global__ void presplit_all(const float* __restrict__ W1, const float* __restrict__ W2) {
    int i = blockIdx.x * blockDim.x + threadIdx.x;
    const int n1 = 4 * H4 * DH / 2;
    if (i < n1) {
        float2 v = *(const float2*)(W1 + 2 * i);
        ((__half2*)g_W1h)[i] = __floats2half2_rn(v.x, v.y);
    } else if (i < 2 * n1) {
        int j = i - n1;
        float2 v = *(const float2*)(W2 + 2 * j);
        uint32_t h, l;
        split2h(v.x, v.y, h, l);
        ((uint32_t*)g_W2h)[j] = h;
        ((uint32_t*)g_W2l)[j] = l;
    }
}
__global__ void zero_i_k(int* p, int n) {
    int i = blockIdx.x * blockDim.x + threadIdx.x;
    if (i < n) p[i] = 0;
}

// ---------------- CSR build ----------------
__global__ void hist_kernel(const void* ei, int E) {
    int e = blockIdx.x * blockDim.x + threadIdx.x;
    if (e < E) atomicAdd(&g_cursor[readIdx(ei, (long long)E + e)], 1);
}
__global__ void scan1_kernel(int n) {
    __shared__ int s[1024];
    int tid = threadIdx.x;
    int i = blockIdx.x * 1024 + tid;
    int v = (i < n) ? g_cursor[i] : 0;
    s[tid] = v;
    __syncthreads();
    for (int off = 1; off < 1024; off <<= 1) {
        int t = 0;
        if (tid >= off) t = s[tid - off];
        __syncthreads();
        s[tid] += t;
        __syncthreads();
    }
    if (i < n) g_rowptr[i + 1] = s[tid];
    if (tid == 1023) g_bsum[blockIdx.x] = s[1023];
}
__global__ void scan2_kernel(int nb) {
    if (threadIdx.x == 0) {
        int run = 0;
        for (int b = 0; b < nb; b++) { g_boff[b] = run; run += g_bsum[b]; }
    }
}
__global__ void scan3_kernel(int n) {
    int i = blockIdx.x * blockDim.x + threadIdx.x;
    if (i < n) g_rowptr[i + 1] += g_boff[i >> 10];
    if (i == 0) g_rowptr[0] = 0;
}
__global__ void scatter_kernel(const void* ei, int E) {
    int e = blockIdx.x * blockDim.x + threadIdx.x;
    if (e >= E) return;
    int d = readIdx(ei, (long long)E + e);
    int slot = g_rowptr[d] + atomicAdd(&g_cursor[d], 1);
    g_colidx[slot] = readIdx(ei, e);
}

// ---------------- graph ranges ----------------
__global__ void gstart_kernel(const void* batch, int n) {
    int g = blockIdx.x * blockDim.x + threadIdx.x;
    if (g > NG) return;
    int lo = 0, hi = n;
    while (lo < hi) {
        int mid = (lo + hi) >> 1;
        if (readIdx(batch, mid) < g) lo = mid + 1; else hi = mid;
    }
    g_gstart[g] = lo;
}
__global__ void invcnt_kernel() {
    int g = threadIdx.x;
    if (g < NG) {
        int c = g_gstart[g + 1] - g_gstart[g];
        g_invcnt[g] = 1.f / fmaxf((float)c, 1.f);
    }
}

// ---------------- GIN aggregation -> split fp16 A (+ stat zeroing) ----------------
__global__ void agg_kernel(const float* __restrict__ h, int N) {
    if (blockIdx.x == 0) {
        for (int i = threadIdx.x; i < 2 * H4; i += blockDim.x) g_bnstat[i] = 0.f;
    }
    if (blockIdx.x < 32) {
        int base = blockIdx.x * 1024;
        for (int i = threadIdx.x; i < 1024; i += blockDim.x) {
            g_gsum[base + i] = 0.f;
            g_gsq[base + i] = 0.f;
        }
    }
    int warp = (blockIdx.x * blockDim.x + threadIdx.x) >> 5;
    int lane = threadIdx.x & 31;
    if (warp >= N) return;
    float4 acc = __ldg((const float4*)(h + (size_t)warp * DH) + lane);
    int s = g_rowptr[warp], e = g_rowptr[warp + 1];
    for (int p = s; p < e; ++p) {
        int nb = g_colidx[p];
        float4 v = __ldg((const float4*)(h + (size_t)nb * DH) + lane);
        acc.x += v.x; acc.y += v.y; acc.z += v.z; acc.w += v.w;
    }
    uint32_t h0, l0, h1, l1;
    split2h(acc.x, acc.y, h0, l0);
    split2h(acc.z, acc.w, h1, l1);
    ((uint2*)(g_Ah + (size_t)warp * DH))[lane] = make_uint2(h0, h1);
    ((uint2*)(g_Al + (size_t)warp * DH))[lane] = make_uint2(l0, l1);
}

// ---------------- GraphNorm: 4-slice stats, then fused finalize+apply+pool -------
__global__ void gstats_kernel() {
    int g = blockIdx.x, sl = blockIdx.y, f = threadIdx.x;
    int s = g_gstart[g], e = g_gstart[g + 1];
    float sum = 0.f, sq = 0.f;
    for (int r = s + sl; r < e; r += 4) {
        float v = g_z2[(size_t)r * DH + f];
        sum += v; sq += v * v;
    }
    if (sum != 0.f || sq != 0.f) {
        atomicAdd(&g_gsum[g * DH + f], sum);
        atomicAdd(&g_gsq[g * DH + f], sq);
    }
}
__global__ void final_kernel(const float* __restrict__ gn_g,
                             const float* __restrict__ gn_b,
                             const float* __restrict__ gn_a,
                             float* __restrict__ out, int l) {
    int g = blockIdx.x, sl = blockIdx.y, f = threadIdx.x;
    int s = g_gstart[g], e = g_gstart[g + 1];
    float ic = g_invcnt[g];
    float mu = g_gsum[g * DH + f] * ic;
    float am = __ldg(&gn_a[f]) * mu;
    float var = fmaxf(g_gsq[g * DH + f] * ic - 2.f * am * mu + am * am, 0.f);
    float rstd = rsqrtf(var + GN_EPS);
    float GS = __ldg(&gn_g[f]) * rstd;
    float GB = __ldg(&gn_b[f]) - am * GS;
    float acc = 0.f;
    bool any = false;
    for (int r = s + sl; r < e; r += 4) {
        float val = selu_f(fmaf(g_z2[(size_t)r * DH + f], GS, GB));
        g_h[(size_t)r * DH + f] = val;
        acc += val;
        any = true;
    }
    if (any)
        atomicAdd(&out[(size_t)g * H4 + l * DH + f], acc * ic);
}

// ---------------- launch ----------------
extern "C" void kernel_launch(void* const* d_in, const int* in_sizes, int n_in,
                              void* d_out, int out_size) {
    const float* x    = (const float*)d_in[0];
    const float* W1   = (const float*)d_in[1];
    const float* bn_g = (const float*)d_in[2];
    const float* bn_b = (const float*)d_in[3];
    const float* W2   = (const float*)d_in[4];
    const float* b2   = (const float*)d_in[5];
    const float* gn_g = (const float*)d_in[6];
    const float* gn_b = (const float*)d_in[7];
    const float* gn_a = (const float*)d_in[8];
    const void*  ei   = d_in[9];
    const void*  batch= d_in[10];
    int N = in_sizes[0] / DH;
    int E = in_sizes[9] / 2;
    float* out = (float*)d_out;

    float *pz1, *pz2, *ph;
    int* pcur;
    __half *pW1h, *pW2h, *pW2l;
    cudaGetSymbolAddress((void**)&pz1, g_z1);
    cudaGetSymbolAddress((void**)&pz2, g_z2);
    cudaGetSymbolAddress((void**)&ph,  g_h);
    cudaGetSymbolAddress((void**)&pcur, g_cursor);
    cudaGetSymbolAddress((void**)&pW1h, g_W1h);
    cudaGetSymbolAddress((void**)&pW2h, g_W2h);
    cudaGetSymbolAddress((void**)&pW2l, g_W2l);

    cudaFuncSetAttribute(mgemm1, cudaFuncAttributeMaxDynamicSharedMemorySize, SMEM_G1);
    cudaFuncSetAttribute(mgemm2, cudaFuncAttributeMaxDynamicSharedMemorySize, SMEM_G2);

    int zb = (out_size > N ? out_size : N);
    detect_zero_k<<<(zb + 255) / 256, 256>>>(ei, N, out, out_size);
    presplit_all<<<1024, 256>>>(W1, W2);
    gstart_kernel<<<2, 256>>>(batch, N);
    hist_kernel<<<(E + 255) / 256, 256>>>(ei, E);
    int nb = (N + 1023) / 1024;
    scan1_kernel<<<nb, 1024>>>(N);
    scan2_kernel<<<1, 32>>>(nb);
    scan3_kernel<<<(N + 255) / 256, 256>>>(N);
    zero_i_k<<<(N + 255) / 256, 256>>>(pcur, N);
    scatter_kernel<<<(E + 255) / 256, 256>>>(ei, E);
    invcnt_kernel<<<1, 256>>>();

    int gm = (N + 127) / 128;
    float invN = 1.f / (float)N;
    for (int l = 0; l < 4; l++) {
        const float* hin = l ? (const float*)ph : x;
        agg_kernel<<<(N + 7) / 8, 256>>>(hin, N);
        mgemm1<<<dim3(4, gm), 256, SMEM_G1>>>(
            pW1h + (size_t)l * H4 * DH, pz1, N, DH, H4);
        mgemm2<<<dim3(1, gm), 256, SMEM_G2>>>(
            pz1, pW2h + (size_t)l * DH * H4, pW2l + (size_t)l * DH * H4,
            pz2, N, H4, DH, b2 + l * DH, bn_g + l * H4, bn_b + l * H4, invN);
        gstats_kernel<<<dim3(NG, 4), 128>>>();
        final_kernel<<<dim3(NG, 4), 128>>>(gn_g + l * DH, gn_b + l * DH,
                                           gn_a + l * DH, out, l);
    }
}

// round 17
// speedup vs baseline: 1.0033x; 1.0033x over previous
#include <cuda_runtime.h>
#include <cuda_fp16.h>
#include <mma.h>
#include <cstdint>
#include <cstddef>

#define NMAX 100000
#define EMAX 600000
#define NG   256
#define DH   128
#define H4   512
#define BN_EPS 1e-5f
#define GN_EPS 1e-5f

using namespace nvcuda;

// ---------------- static device scratch ----------------
static __device__ __half g_Ah[(size_t)NMAX * DH];
static __device__ __half g_Al[(size_t)NMAX * DH];
static __device__ float g_z1[(size_t)NMAX * H4];
static __device__ float g_z2[(size_t)NMAX * DH];
static __device__ float g_h [(size_t)NMAX * DH];
static __device__ __half g_W1h[4 * H4 * DH];
static __device__ __half g_W2h[4 * DH * H4];
static __device__ __half g_W2l[4 * DH * H4];
static __device__ int   g_rowptr[NMAX + 1];
static __device__ int   g_cursor[NMAX];
static __device__ int   g_colidx[EMAX];
static __device__ int   g_bsum[128];
static __device__ int   g_boff[128];
static __device__ int   g_gstart[NG + 1];
static __device__ float g_invcnt[NG];
static __device__ float g_bnstat[2 * H4];
static __device__ float g_gsum[NG * DH];
static __device__ float g_gsq[NG * DH];
static __device__ int   g_i64;

// ---------------- helpers ----------------
__device__ __forceinline__ float selu_f(float x) {
    const float lam = 1.0507009873554805f;
    const float la  = 1.7580993408473766f;
    return x > 0.f ? lam * x : la * (__expf(x) - 1.f);
}
__device__ __forceinline__ int readIdx(const void* p, long long i) {
    return g_i64 ? (int)((const long long*)p)[i] : ((const int*)p)[i];
}
__device__ __forceinline__ void split2h(float a, float b, uint32_t& hi, uint32_t& lo) {
    __half2 H = __floats2half2_rn(a, b);
    float2 F = __half22float2(H);
    __half2 L = __floats2half2_rn(a - F.x, b - F.y);
    hi = *(uint32_t*)&H;
    lo = *(uint32_t*)&L;
}
__device__ __forceinline__ void cpa16(uint32_t dst, const void* src, int srcsz) {
    asm volatile("cp.async.cg.shared.global [%0], [%1], 16, %2;"
                 :: "r"(dst), "l"(src), "r"(srcsz));
}
#define CPA_COMMIT() asm volatile("cp.async.commit_group;" ::: "memory")
#define CPA_WAIT0()  asm volatile("cp.async.wait_group 0;" ::: "memory")
#define CPA_WAIT1()  asm volatile("cp.async.wait_group 1;" ::: "memory")

// K=32 chunk tiles: 128 rows x 32 fp16, row stride 40 elems (80B)
#define LDA2 40
#define ROWB 80
#define T32  10240
#define SET_G1 (3 * T32)                // {Ah, Al, Bh} = 30720
#define SET_G2 (4 * T32)                // {Ah, Al, Bh, Bl} = 40960
#define SMEM_G1 67584                   // >= 2*SET_G1 and Csm (128*132*4)
#define G2_STG  (2 * SET_G2)            // 81920
#define SMEM_G2 (G2_STG + 128 * 144)    // 100352
#define LDC 132

// ---------------- MMA for one 128x128x32 chunk; warp tile 32x64 ----------------
template <int TERMS>
__device__ __forceinline__ void mma_chunk32(
    const char* bc, int m0, int n0,
    wmma::fragment<wmma::accumulator, 16, 16, 16, float> acc[2][4]) {
    const __half* Ah = (const __half*)bc;
    const __half* Al = (const __half*)(bc + T32);
    const __half* Bh = (const __half*)(bc + 2 * T32);
    const __half* Bl = (const __half*)(bc + 3 * T32);
#pragma unroll
    for (int ks = 0; ks < 2; ks++) {
        wmma::fragment<wmma::matrix_a, 16, 16, 16, __half, wmma::row_major> ah[2], al[2];
#pragma unroll
        for (int mi = 0; mi < 2; mi++) {
            wmma::load_matrix_sync(ah[mi], Ah + (m0 + 16 * mi) * LDA2 + ks * 16, LDA2);
            wmma::load_matrix_sync(al[mi], Al + (m0 + 16 * mi) * LDA2 + ks * 16, LDA2);
        }
#pragma unroll
        for (int ni = 0; ni < 4; ni++) {
            wmma::fragment<wmma::matrix_b, 16, 16, 16, __half, wmma::col_major> bh, bl;
            wmma::load_matrix_sync(bh, Bh + (n0 + 16 * ni) * LDA2 + ks * 16, LDA2);
            if (TERMS == 3)
                wmma::load_matrix_sync(bl, Bl + (n0 + 16 * ni) * LDA2 + ks * 16, LDA2);
#pragma unroll
            for (int mi = 0; mi < 2; mi++) {
                wmma::mma_sync(acc[mi][ni], ah[mi], bh, acc[mi][ni]);
                wmma::mma_sync(acc[mi][ni], al[mi], bh, acc[mi][ni]);
                if (TERMS == 3)
                    wmma::mma_sync(acc[mi][ni], ah[mi], bl, acc[mi][ni]);
            }
        }
    }
}

// ---------------- GEMM1: 2-term, all-copy loader {Ah, Al, Bh} ----------------
__device__ __forceinline__ void issueG1(const __half* __restrict__ Bh,
                                        int K, int rowBase, int M, int colBase,
                                        int kbase, uint32_t sb, int tid) {
#pragma unroll
    for (int i = 0; i < 6; i++) {       // 3 tiles x 128 rows x 4 k16
        int c = tid + i * 256;
        int tile = c >> 9, r = (c >> 2) & 127, k16 = c & 3;
        uint32_t dst = sb + tile * T32 + r * ROWB + k16 * 16;
        const __half* src;
        int sz = 16;
        if (tile < 2) {
            int gr = rowBase + r;
            int cl = gr < M ? gr : (M - 1);
            sz = gr < M ? 16 : 0;
            src = (tile ? g_Al : g_Ah) + (size_t)cl * K + kbase + k16 * 8;
        } else {
            src = Bh + (size_t)(colBase + r) * K + kbase + k16 * 8;
        }
        cpa16(dst, src, sz);
    }
    CPA_COMMIT();
}

__global__ void __launch_bounds__(256, 2)
mgemm1(const __half* __restrict__ Bh, float* __restrict__ C, int M, int K, int Ncols) {
    extern __shared__ char sm[];
    uint32_t sb = (uint32_t)__cvta_generic_to_shared(sm);
    int tid = threadIdx.x;
    int w = tid >> 5;
    int m0 = (w >> 1) * 32, n0 = (w & 1) * 64;
    int rowBase = blockIdx.y * 128;
    int colBase = blockIdx.x * 128;

    wmma::fragment<wmma::accumulator, 16, 16, 16, float> acc[2][4];
#pragma unroll
    for (int mi = 0; mi < 2; mi++)
#pragma unroll
        for (int ni = 0; ni < 4; ni++) wmma::fill_fragment(acc[mi][ni], 0.f);

    int nch = K >> 5;       // 4
    issueG1(Bh, K, rowBase, M, colBase, 0, sb, tid);
    for (int ch = 0; ch < nch; ch++) {
        if (ch + 1 < nch) {
            issueG1(Bh, K, rowBase, M, colBase, (ch + 1) * 32,
                    sb + ((ch + 1) & 1) * SET_G1, tid);
            CPA_WAIT1();
        } else {
            CPA_WAIT0();
        }
        __syncthreads();
        mma_chunk32<2>(sm + (ch & 1) * SET_G1, m0, n0, acc);
        __syncthreads();
    }

    // epilogue: stage in smem, write C, BN stats
    float* Csm = (float*)sm;
#pragma unroll
    for (int mi = 0; mi < 2; mi++)
#pragma unroll
        for (int ni = 0; ni < 4; ni++)
            wmma::store_matrix_sync(Csm + (m0 + 16 * mi) * LDC + n0 + 16 * ni,
                                    acc[mi][ni], LDC, wmma::mem_row_major);
    __syncthreads();
    {
        int row = tid >> 1;
        int cb = (tid & 1) * 64;
        int grow = rowBase + row;
        if (grow < M) {
            float* dst = C + (size_t)grow * Ncols + colBase + cb;
            const float* srcr = Csm + row * LDC + cb;
#pragma unroll
            for (int j = 0; j < 64; j += 4)
                *(float4*)(dst + j) = *(const float4*)(srcr + j);
        }
    }
    {
        int c = tid & 127;
        int r0 = (tid >> 7) * 64;
        float s = 0.f, q = 0.f;
#pragma unroll 4
        for (int r = r0; r < r0 + 64; r++) {
            float v = Csm[r * LDC + c];
            s += v; q += v * v;
        }
        atomicAdd(&g_bnstat[colBase + c], s);
        atomicAdd(&g_bnstat[H4 + colBase + c], q);
    }
}

// ---------------- GEMM2: 3-term, staged fp32 A -> fused BN+SELU+split ----------
__device__ __forceinline__ void issueA2(const float* __restrict__ A, int K,
                                        int rowBase, int M, int kbase,
                                        uint32_t sb, int tid) {
#pragma unroll
    for (int i = 0; i < 4; i++) {
        int c = tid + i * 256;
        int row = c >> 3, j = c & 7;
        int gr = rowBase + row;
        int cl = gr < M ? gr : (M - 1);
        int sz = gr < M ? 16 : 0;
        cpa16(sb + G2_STG + row * 144 + j * 16,
              A + (size_t)cl * K + kbase + j * 4, sz);
    }
}
__device__ __forceinline__ void issueB2(const __half* __restrict__ Bh,
                                        const __half* __restrict__ Bl,
                                        int K, int kbase, uint32_t sbset, int tid) {
#pragma unroll
    for (int i = 0; i < 4; i++) {
        int c = tid + i * 256;
        int half_ = c >> 9, r = (c >> 2) & 127, k16 = c & 3;
        const __half* src = (half_ ? Bl : Bh) + (size_t)r * K + kbase + k16 * 8;
        cpa16(sbset + (2 + half_) * T32 + r * ROWB + k16 * 16, src, 16);
    }
}
__device__ __forceinline__ void convertA(char* sm, char* dset, int kbase, int tid,
                                         const float* s_sc, const float* s_sh) {
    int kc = tid & 15;
    int rg = tid >> 4;
    float s0 = s_sc[kbase + 2 * kc],     b0 = s_sh[kbase + 2 * kc];
    float s1 = s_sc[kbase + 2 * kc + 1], b1 = s_sh[kbase + 2 * kc + 1];
    const char* stg = sm + G2_STG;
    char* tah = dset;
    char* tal = dset + T32;
#pragma unroll
    for (int rr = 0; rr < 8; rr++) {
        int row = rg * 8 + rr;
        float2 v = *(const float2*)(stg + row * 144 + kc * 8);
        float a = selu_f(fmaf(v.x, s0, b0));
        float b = selu_f(fmaf(v.y, s1, b1));
        uint32_t h, l;
        split2h(a, b, h, l);
        *(uint32_t*)(tah + row * ROWB + kc * 4) = h;
        *(uint32_t*)(tal + row * ROWB + kc * 4) = l;
    }
}

__global__ void __launch_bounds__(256, 2)
mgemm2(const float* __restrict__ A, const __half* __restrict__ Bh,
       const __half* __restrict__ Bl,
       float* __restrict__ C, int M, int K, int Ncols, const float* __restrict__ bias,
       const float* __restrict__ bn_g, const float* __restrict__ bn_b, float invN) {
    extern __shared__ char sm[];
    __shared__ float s_sc[H4], s_sh[H4];
    uint32_t sb = (uint32_t)__cvta_generic_to_shared(sm);
    int tid = threadIdx.x;
    int w = tid >> 5;
    int m0 = (w >> 1) * 32, n0 = (w & 1) * 64;
    int rowBase = blockIdx.y * 128;

    for (int i = tid; i < H4; i += 256) {
        float mu = g_bnstat[i] * invN;
        float var = fmaxf(g_bnstat[H4 + i] * invN - mu * mu, 0.f);
        float rstd = rsqrtf(var + BN_EPS);
        float sc = __ldg(&bn_g[i]) * rstd;
        s_sc[i] = sc;
        s_sh[i] = __ldg(&bn_b[i]) - mu * sc;
    }

    wmma::fragment<wmma::accumulator, 16, 16, 16, float> acc[2][4];
#pragma unroll
    for (int mi = 0; mi < 2; mi++)
#pragma unroll
        for (int ni = 0; ni < 4; ni++) wmma::fill_fragment(acc[mi][ni], 0.f);

    int nch = K >> 5;       // 16
    issueA2(A, K, rowBase, M, 0, sb, tid);
    issueB2(Bh, Bl, K, 0, sb, tid);
    CPA_COMMIT();
    CPA_WAIT0();
    __syncthreads();
    convertA(sm, sm, 0, tid, s_sc, s_sh);
    __syncthreads();

    for (int ch = 0; ch < nch; ch++) {
        if (ch + 1 < nch) {
            issueA2(A, K, rowBase, M, (ch + 1) * 32, sb, tid);
            issueB2(Bh, Bl, K, (ch + 1) * 32, sb + ((ch + 1) & 1) * SET_G2, tid);
            CPA_COMMIT();
        }
        mma_chunk32<3>(sm + (ch & 1) * SET_G2, m0, n0, acc);
        if (ch + 1 < nch) {
            CPA_WAIT0();
            __syncthreads();
            convertA(sm, sm + ((ch + 1) & 1) * SET_G2, (ch + 1) * 32, tid, s_sc, s_sh);
        }
        __syncthreads();
    }

    float* Csm = (float*)sm;
#pragma unroll
    for (int mi = 0; mi < 2; mi++)
#pragma unroll
        for (int ni = 0; ni < 4; ni++)
            wmma::store_matrix_sync(Csm + (m0 + 16 * mi) * LDC + n0 + 16 * ni,
                                    acc[mi][ni], LDC, wmma::mem_row_major);
    __syncthreads();
    {
        int row = tid >> 1;
        int cb = (tid & 1) * 64;
        int grow = rowBase + row;
        if (grow < M) {
            float* dst = C + (size_t)grow * Ncols + cb;
            const float* srcr = Csm + row * LDC + cb;
#pragma unroll
            for (int j = 0; j < 64; j += 4) {
                float4 v = *(const float4*)(srcr + j);
                v.x += __ldg(&bias[cb + j + 0]);
                v.y += __ldg(&bias[cb + j + 1]);
                v.z += __ldg(&bias[cb + j + 2]);
                v.w += __ldg(&bias[cb + j + 3]);
                *(float4*)(dst + j) = v;
            }
        }
    }
}

// ---------------- setup kernels ----------------
__global__ void detect_zero_k(const void* ei, int n, float* out, int outn) {
    int i = blockIdx.x * blockDim.x + threadIdx.x;
    if (i < n) g_cursor[i] = 0;
    if (i < outn) out[i] = 0.f;
    if (i == 0) {
        const long long* p = (const long long*)ei;
        int ok = 1;
        for (int j = 0; j < 64; j++) {
            long long v = p[j];
            if (v < 0 || v >= (1LL << 31)) ok = 0;
        }
        g_i64 = ok;
    }
}
__global__ void presplit_all(const float* __restrict__ W1, const float* __restrict__ W2) {
    int i = blockIdx.x * blockDim.x + threadIdx.x;
    const int n1 = 4 * H4 * DH / 2;
    if (i < n1) {
        float2 v = *(const float2*)(W1 + 2 * i);
        ((__half2*)g_W1h)[i] = __floats2half2_rn(v.x, v.y);
    } else if (i < 2 * n1) {
        int j = i - n1;
        float2 v = *(const float2*)(W2 + 2 * j);
        uint32_t h, l;
        split2h(v.x, v.y, h, l);
        ((uint32_t*)g_W2h)[j] = h;
        ((uint32_t*)g_W2l)[j] = l;
    }
}

// ---------------- CSR build ----------------
__global__ void hist_kernel(const void* ei, int E) {
    int e = blockIdx.x * blockDim.x + threadIdx.x;
    if (e < E) atomicAdd(&g_cursor[readIdx(ei, (long long)E + e)], 1);
}
__global__ void scan1_kernel(int n) {
    __shared__ int s[1024];
    int tid = threadIdx.x;
    int i = blockIdx.x * 1024 + tid;
    int v = (i < n) ? g_cursor[i] : 0;
    s[tid] = v;
    __syncthreads();
    for (int off = 1; off < 1024; off <<= 1) {
        int t = 0;
        if (tid >= off) t = s[tid - off];
        __syncthreads();
        s[tid] += t;
        __syncthreads();
    }
    if (i < n) g_rowptr[i + 1] = s[tid];
    if (tid == 1023) g_bsum[blockIdx.x] = s[1023];
}
__global__ void scan2_kernel(int nb) {
    if (threadIdx.x == 0) {
        int run = 0;
        for (int b = 0; b < nb; b++) { g_boff[b] = run; run += g_bsum[b]; }
    }
}
__global__ void scan3_kernel(int n) {
    int i = blockIdx.x * blockDim.x + threadIdx.x;
    if (i < n) {
        g_rowptr[i + 1] += g_boff[i >> 10];
        g_cursor[i] = 0;        // folded cursor re-zero (scan1 already consumed it)
    }
    if (i == 0) g_rowptr[0] = 0;
}
__global__ void scatter_kernel(const void* ei, int E) {
    int e = blockIdx.x * blockDim.x + threadIdx.x;
    if (e >= E) return;
    int d = readIdx(ei, (long long)E + e);
    int slot = g_rowptr[d] + atomicAdd(&g_cursor[d], 1);
    g_colidx[slot] = readIdx(ei, e);
}

// ---------------- graph ranges ----------------
__global__ void gstart_kernel(const void* batch, int n) {
    int g = blockIdx.x * blockDim.x + threadIdx.x;
    if (g > NG) return;
    int lo = 0, hi = n;
    while (lo < hi) {
        int mid = (lo + hi) >> 1;
        if (readIdx(batch, mid) < g) lo = mid + 1; else hi = mid;
    }
    g_gstart[g] = lo;
}
__global__ void invcnt_kernel() {
    int g = threadIdx.x;
    if (g < NG) {
        int c = g_gstart[g + 1] - g_gstart[g];
        g_invcnt[g] = 1.f / fmaxf((float)c, 1.f);
    }
}

// ---------------- GIN aggregation -> split fp16 A (+ stat zeroing) ----------------
__global__ void agg_kernel(const float* __restrict__ h, int N) {
    if (blockIdx.x == 0) {
        for (int i = threadIdx.x; i < 2 * H4; i += blockDim.x) g_bnstat[i] = 0.f;
    }
    if (blockIdx.x < 32) {
        int base = blockIdx.x * 1024;
        for (int i = threadIdx.x; i < 1024; i += blockDim.x) {
            g_gsum[base + i] = 0.f;
            g_gsq[base + i] = 0.f;
        }
    }
    int warp = (blockIdx.x * blockDim.x + threadIdx.x) >> 5;
    int lane = threadIdx.x & 31;
    if (warp >= N) return;
    float4 acc = __ldg((const float4*)(h + (size_t)warp * DH) + lane);
    int s = g_rowptr[warp], e = g_rowptr[warp + 1];
    for (int p = s; p < e; ++p) {
        int nb = g_colidx[p];
        float4 v = __ldg((const float4*)(h + (size_t)nb * DH) + lane);
        acc.x += v.x; acc.y += v.y; acc.z += v.z; acc.w += v.w;
    }
    uint32_t h0, l0, h1, l1;
    split2h(acc.x, acc.y, h0, l0);
    split2h(acc.z, acc.w, h1, l1);
    ((uint2*)(g_Ah + (size_t)warp * DH))[lane] = make_uint2(h0, h1);
    ((uint2*)(g_Al + (size_t)warp * DH))[lane] = make_uint2(l0, l1);
}

// ---------------- GraphNorm: 4-slice stats, then fused finalize+apply+pool -------
__global__ void gstats_kernel() {
    int g = blockIdx.x, sl = blockIdx.y, f = threadIdx.x;
    int s = g_gstart[g], e = g_gstart[g + 1];
    float sum = 0.f, sq = 0.f;
    for (int r = s + sl; r < e; r += 4) {
        float v = g_z2[(size_t)r * DH + f];
        sum += v; sq += v * v;
    }
    if (sum != 0.f || sq != 0.f) {
        atomicAdd(&g_gsum[g * DH + f], sum);
        atomicAdd(&g_gsq[g * DH + f], sq);
    }
}
__global__ void final_kernel(const float* __restrict__ gn_g,
                             const float* __restrict__ gn_b,
                             const float* __restrict__ gn_a,
                             float* __restrict__ out, int l) {
    int g = blockIdx.x, sl = blockIdx.y, f = threadIdx.x;
    int s = g_gstart[g], e = g_gstart[g + 1];
    float ic = g_invcnt[g];
    float mu = g_gsum[g * DH + f] * ic;
    float am = __ldg(&gn_a[f]) * mu;
    float var = fmaxf(g_gsq[g * DH + f] * ic - 2.f * am * mu + am * am, 0.f);
    float rstd = rsqrtf(var + GN_EPS);
    float GS = __ldg(&gn_g[f]) * rstd;
    float GB = __ldg(&gn_b[f]) - am * GS;
    float acc = 0.f;
    bool any = false;
    for (int r = s + sl; r < e; r += 4) {
        float val = selu_f(fmaf(g_z2[(size_t)r * DH + f], GS, GB));
        g_h[(size_t)r * DH + f] = val;
        acc += val;
        any = true;
    }
    if (any)
        atomicAdd(&out[(size_t)g * H4 + l * DH + f], acc * ic);
}

// ---------------- launch ----------------
extern "C" void kernel_launch(void* const* d_in, const int* in_sizes, int n_in,
                              void* d_out, int out_size) {
    const float* x    = (const float*)d_in[0];
    const float* W1   = (const float*)d_in[1];
    const float* bn_g = (const float*)d_in[2];
    const float* bn_b = (const float*)d_in[3];
    const float* W2   = (const float*)d_in[4];
    const float* b2   = (const float*)d_in[5];
    const float* gn_g = (const float*)d_in[6];
    const float* gn_b = (const float*)d_in[7];
    const float* gn_a = (const float*)d_in[8];
    const void*  ei   = d_in[9];
    const void*  batch= d_in[10];
    int N = in_sizes[0] / DH;
    int E = in_sizes[9] / 2;
    float* out = (float*)d_out;

    float *pz1, *pz2, *ph;
    __half *pW1h, *pW2h, *pW2l;
    cudaGetSymbolAddress((void**)&pz1, g_z1);
    cudaGetSymbolAddress((void**)&pz2, g_z2);
    cudaGetSymbolAddress((void**)&ph,  g_h);
    cudaGetSymbolAddress((void**)&pW1h, g_W1h);
    cudaGetSymbolAddress((void**)&pW2h, g_W2h);
    cudaGetSymbolAddress((void**)&pW2l, g_W2l);

    cudaFuncSetAttribute(mgemm1, cudaFuncAttributeMaxDynamicSharedMemorySize, SMEM_G1);
    cudaFuncSetAttribute(mgemm2, cudaFuncAttributeMaxDynamicSharedMemorySize, SMEM_G2);

    int zb = (out_size > N ? out_size : N);
    detect_zero_k<<<(zb + 255) / 256, 256>>>(ei, N, out, out_size);
    presplit_all<<<1024, 256>>>(W1, W2);
    gstart_kernel<<<2, 256>>>(batch, N);
    hist_kernel<<<(E + 255) / 256, 256>>>(ei, E);
    int nb = (N + 1023) / 1024;
    scan1_kernel<<<nb, 1024>>>(N);
    scan2_kernel<<<1, 32>>>(nb);
    scan3_kernel<<<(N + 255) / 256, 256>>>(N);
    scatter_kernel<<<(E + 255) / 256, 256>>>(ei, E);
    invcnt_kernel<<<1, 256>>>();

    int gm = (N + 127) / 128;
    float invN = 1.f / (float)N;
    for (int l = 0; l < 4; l++) {
        const float* hin = l ? (const float*)ph : x;
        agg_kernel<<<(N + 7) / 8, 256>>>(hin, N);
        mgemm1<<<dim3(4, gm), 256, SMEM_G1>>>(
            pW1h + (size_t)l * H4 * DH, pz1, N, DH, H4);
        mgemm2<<<dim3(1, gm), 256, SMEM_G2>>>(
            pz1, pW2h + (size_t)l * DH * H4, pW2l + (size_t)l * DH * H4,
            pz2, N, H4, DH, b2 + l * DH, bn_g + l * H4, bn_b + l * H4, invN);
        gstats_kernel<<<dim3(NG, 4), 128>>>();
        final_kernel<<<dim3(NG, 4), 128>>>(gn_g + l * DH, gn_b + l * DH,
                                           gn_a + l * DH, out, l);
    }
}